// round 3
// baseline (speedup 1.0000x reference)
#include <cuda_runtime.h>
#include <cuda_bf16.h>
#include <cstdint>

// Embedding gather: out[r, :] = weight[indices[r], :]
// indices: [4096*200]=819200 int32, weight: [1,000,000 x 128] f32,
// out: [819200 x 128] f32.
//
// One thread per 16B (float4) chunk: row = tid>>5, lane = tid&31.
// - weight loads: default-cached (L2 reuse from duplicate indices, ~1.46 refs/row)
// - output stores: __stcs streaming hint so the 419MB write stream doesn't
//   evict weight lines from L2.
// - all-32-bit addressing (26.2M chunks < 2^31) -> no IMAD.WIDE chains.
// Pure HBM-bound; expect ~105-130us (roofline ~100us at 8TB/s).

__global__ __launch_bounds__(512, 4)
void embedding_gather_kernel(const int* __restrict__ indices,
                             const float4* __restrict__ weight,
                             float4* __restrict__ out,
                             int total_chunks)
{
    int tid = blockIdx.x * blockDim.x + threadIdx.x;
    if (tid >= total_chunks) return;          // never diverges: grid divides exactly

    int row  = tid >> 5;
    int lane = tid & 31;

    int idx = __ldg(&indices[row]);           // warp-uniform broadcast load
    int src = idx * 32 + lane;                // < 32M, fits int

    float4 v = __ldg(&weight[src]);
    __stcs(&out[tid], v);                     // streaming store: keep L2 for weight
}

extern "C" void kernel_launch(void* const* d_in, const int* in_sizes, int n_in,
                              void* d_out, int out_size)
{
    const int* indices = nullptr;
    const float4* weight = nullptr;
    int num_rows = 0;

    // Robust to either input ordering: indices is the small int32 array.
    if (in_sizes[0] < in_sizes[1]) {
        indices = (const int*)d_in[0];
        weight  = (const float4*)d_in[1];
        num_rows = in_sizes[0];
    } else {
        indices = (const int*)d_in[1];
        weight  = (const float4*)d_in[0];
        num_rows = in_sizes[1];
    }

    float4* out = (float4*)d_out;

    int total_chunks = num_rows * 32;         // 26,214,400 for the bench shape
    int block = 512;
    int grid = (total_chunks + block - 1) / block;

    embedding_gather_kernel<<<grid, block>>>(indices, weight, out, total_chunks);
}

// round 10
// speedup vs baseline: 1.3309x; 1.3309x over previous
#include <cuda_runtime.h>
#include <cuda_bf16.h>
#include <cstdint>

// Embedding gather: out[r, :] = weight[indices[r], :]
// indices: [819200] int32, weight: [1,000,000 x 128] f32, out: [819200 x 128] f32.
//
// R3 measured: 1 LDG/thread -> in-flight bytes/SM (~23KB) sat at the
// latency-BW knee (577cyc x 43B/cyc ~ 25KB) -> DRAM stuck at 59.7%, 164us.
// Fix (awaiting bench, GPU timeouts R4-R9): UNROLL=4 independent chunks per
// thread (grid-strided, coalescing preserved), front-batched LDG.128s ->
// ~90KB in flight/SM. Predict DRAM% -> 85%+, dur -> ~115us.

#define UNROLL 4

__global__ __launch_bounds__(256, 8)
void embedding_gather_kernel(const int* __restrict__ indices,
                             const float4* __restrict__ weight,
                             float4* __restrict__ out,
                             int total_chunks)
{
    int tid    = blockIdx.x * blockDim.x + threadIdx.x;
    int stride = gridDim.x * blockDim.x;       // = total_chunks / UNROLL (exact)

    int    c[UNROLL];
    int    src[UNROLL];
    float4 v[UNROLL];

    #pragma unroll
    for (int u = 0; u < UNROLL; u++) {
        c[u] = tid + u * stride;
        int row  = c[u] >> 5;                  // 32 float4 chunks per 128-f32 row
        int lane = c[u] & 31;
        int idx  = __ldg(&indices[row]);       // warp-uniform broadcast
        src[u] = idx * 32 + lane;              // < 32M, fits int32
    }

    // Front-batched independent loads: 4 x 512B wavefronts in flight per warp
    #pragma unroll
    for (int u = 0; u < UNROLL; u++)
        v[u] = __ldg(&weight[src[u]]);

    #pragma unroll
    for (int u = 0; u < UNROLL; u++)
        __stcs(&out[c[u]], v[u]);              // streaming store: keep L2 for weight
}

extern "C" void kernel_launch(void* const* d_in, const int* in_sizes, int n_in,
                              void* d_out, int out_size)
{
    const int* indices = nullptr;
    const float4* weight = nullptr;
    int num_rows = 0;

    // Robust to either input ordering: indices is the small int32 array.
    if (in_sizes[0] < in_sizes[1]) {
        indices = (const int*)d_in[0];
        weight  = (const float4*)d_in[1];
        num_rows = in_sizes[0];
    } else {
        indices = (const int*)d_in[1];
        weight  = (const float4*)d_in[0];
        num_rows = in_sizes[1];
    }

    float4* out = (float4*)d_out;

    int total_chunks = num_rows * 32;          // 26,214,400 for the bench shape
    int block = 256;
    // 26,214,400 = 256 * 4 * 25600 -> exact division, no tail guard needed
    int grid = total_chunks / (block * UNROLL);

    embedding_gather_kernel<<<grid, block>>>(indices, weight, out, total_chunks);
}